// round 1
// baseline (speedup 1.0000x reference)
#include <cuda_runtime.h>
#include <cuda_bf16.h>
#include <cstdint>

// Problem shapes
#define B_IMG   64
#define H_IMG   256
#define W_IMG   256
#define PATCH   16
#define NPATCH  256            // (256/16)^2 per image
#define D_PATCH 256            // 16*16
#define ROWS    (B_IMG * NPATCH)   // 16384 patch rows
#define VROWS   4096
#define KDIM    256

#define N_PATCH_ELEMS (B_IMG * NPATCH * D_PATCH)   // 4194304
#define N_TOKENS      (B_IMG * NPATCH)             // 16384

// GEMM tiling
#define BM 128
#define BN 128
#define BK 32
#define TM 8
#define TN 8
#define SPAD 132               // padded row stride (floats) for 128-wide smem rows

// Shared memory layout (floats):
//   As   : [256][SPAD]  (K-major, m contiguous)    = 256*132 = 33792
//   Bs   : [2][BK][SPAD]                           = 2*32*132 = 8448
//   redS : [128][16]                               = 2048
//   redI : [128][16] (int)                         = 2048
#define AS_FLOATS   (KDIM * SPAD)
#define BS_FLOATS   (2 * BK * SPAD)
#define RED_FLOATS  (BM * 16)
#define SMEM_FLOATS (AS_FLOATS + BS_FLOATS + RED_FLOATS + RED_FLOATS)
#define SMEM_BYTES  (SMEM_FLOATS * 4)

// Scratch (device-global: no allocation allowed in kernel_launch)
__device__ float g_patches[N_PATCH_ELEMS];
__device__ float g_hv2[VROWS];

// ---------------------------------------------------------------------------
// Kernel 1: patchify. Raster patch order; each thread moves one float4
// (4 contiguous columns within one patch row == contiguous in image memory).
// ---------------------------------------------------------------------------
__global__ void patchify_kernel(const float* __restrict__ img,
                                float* __restrict__ out_opt) {
    int i = blockIdx.x * blockDim.x + threadIdx.x;     // float4 index
    if (i >= N_PATCH_ELEMS / 4) return;
    int f  = i << 2;
    int d  = f & 255;          // element within patch
    int pn = f >> 8;           // b*256 + n
    int b  = pn >> 8;
    int n  = pn & 255;
    int r  = d >> 4, c = d & 15;
    int py = n >> 4, px = n & 15;
    const float4 v = *(const float4*)(img + (size_t)b * (H_IMG * W_IMG)
                                      + (size_t)(py * PATCH + r) * W_IMG
                                      + px * PATCH + c);
    ((float4*)g_patches)[i] = v;
    if (out_opt) ((float4*)out_opt)[i] = v;
}

// ---------------------------------------------------------------------------
// Kernel 2: 0.5 * ||v||^2 per vocab row (one warp per row, shuffle reduce)
// ---------------------------------------------------------------------------
__global__ void vocab_norm_kernel(const float* __restrict__ vocab) {
    int gt   = blockIdx.x * blockDim.x + threadIdx.x;
    int w    = gt >> 5;
    int lane = gt & 31;
    if (w >= VROWS) return;
    const float4* row = (const float4*)(vocab + (size_t)w * KDIM);
    float s = 0.f;
    #pragma unroll
    for (int j = 0; j < 2; j++) {
        float4 q = row[lane + 32 * j];
        s += q.x * q.x + q.y * q.y + q.z * q.z + q.w * q.w;
    }
    #pragma unroll
    for (int off = 16; off; off >>= 1) s += __shfl_xor_sync(0xFFFFFFFFu, s, off);
    if (lane == 0) g_hv2[w] = 0.5f * s;
}

// ---------------------------------------------------------------------------
// Kernel 3: fused GEMM + row-argmax of (x.v - 0.5||v||^2).
// One block per 128 patch rows; loops over all 32 vocab tiles of 128.
// A tile (128 x 256) is SMEM-resident for the whole block; B is streamed in
// double-buffered K=32 chunks (LDG prefetch -> compute -> STS -> bar).
// ---------------------------------------------------------------------------
__global__ void __launch_bounds__(256, 1)
gemm_argmax_kernel(const float* __restrict__ vocab,
                   float* __restrict__ tok_f, int* __restrict__ tok_i) {
    extern __shared__ float sm[];
    float* As   = sm;
    float* Bs   = As + AS_FLOATS;
    float* redS = Bs + BS_FLOATS;
    int*   redI = (int*)(redS + RED_FLOATS);

    const int t  = threadIdx.x;
    const int m0 = blockIdx.x * BM;
    const int tx = t & 15;         // column group
    const int ty = t >> 4;         // row group
    const int mrow = ty * TM;
    const int ncol = tx * TN;

    // ---- Load A tile (128 rows x 256 K) once, transposed to K-major ----
    // 8192 float4 total -> 32 per thread.
    #pragma unroll
    for (int i = 0; i < 32; i++) {
        int f  = t + (i << 8);
        int m  = f >> 6;          // 64 float4 per row
        int k4 = f & 63;
        float4 q = *(const float4*)(g_patches + (size_t)(m0 + m) * KDIM + (k4 << 2));
        int k = k4 << 2;
        As[(k + 0) * SPAD + m] = q.x;
        As[(k + 1) * SPAD + m] = q.y;
        As[(k + 2) * SPAD + m] = q.z;
        As[(k + 3) * SPAD + m] = q.w;
    }
    __syncthreads();

    float best[TM];
    int   bidx[TM];
    #pragma unroll
    for (int i = 0; i < TM; i++) { best[i] = -3.4e38f; bidx[i] = 0; }

    for (int nt = 0; nt < VROWS / BN; nt++) {
        const int n0 = nt << 7;

        // ---- prologue: load + store chunk 0 of B ----
        float4 pre[4];
        #pragma unroll
        for (int i = 0; i < 4; i++) {
            int f  = t + (i << 8);     // 0..1023
            int n  = f >> 3;           // 8 float4 per vocab row per chunk
            int k4 = f & 7;
            pre[i] = *(const float4*)(vocab + (size_t)(n0 + n) * KDIM + (k4 << 2));
        }
        #pragma unroll
        for (int i = 0; i < 4; i++) {
            int f = t + (i << 8);
            int n = f >> 3, k = (f & 7) << 2;
            Bs[(k + 0) * SPAD + n] = pre[i].x;
            Bs[(k + 1) * SPAD + n] = pre[i].y;
            Bs[(k + 2) * SPAD + n] = pre[i].z;
            Bs[(k + 3) * SPAD + n] = pre[i].w;
        }
        __syncthreads();

        float acc[TM][TN];
        #pragma unroll
        for (int i = 0; i < TM; i++)
            #pragma unroll
            for (int j = 0; j < TN; j++) acc[i][j] = 0.f;

        for (int kc = 0; kc < KDIM / BK; kc++) {
            // prefetch next chunk into registers (overlaps with compute)
            if (kc < KDIM / BK - 1) {
                int kbase = (kc + 1) << 5;
                #pragma unroll
                for (int i = 0; i < 4; i++) {
                    int f  = t + (i << 8);
                    int n  = f >> 3;
                    int k4 = f & 7;
                    pre[i] = *(const float4*)(vocab + (size_t)(n0 + n) * KDIM
                                              + kbase + (k4 << 2));
                }
            }
            const float* Bc = Bs + (kc & 1) * (BK * SPAD);
            const int kglob = kc << 5;
            #pragma unroll
            for (int kk = 0; kk < BK; kk++) {
                const float* arow = As + (kglob + kk) * SPAD + mrow;
                const float* brow = Bc + kk * SPAD + ncol;
                float4 a0 = *(const float4*)(arow);
                float4 a1 = *(const float4*)(arow + 4);
                float4 b0 = *(const float4*)(brow);
                float4 b1 = *(const float4*)(brow + 4);
                float a[TM] = {a0.x, a0.y, a0.z, a0.w, a1.x, a1.y, a1.z, a1.w};
                float b[TN] = {b0.x, b0.y, b0.z, b0.w, b1.x, b1.y, b1.z, b1.w};
                #pragma unroll
                for (int i = 0; i < TM; i++)
                    #pragma unroll
                    for (int j = 0; j < TN; j++)
                        acc[i][j] = fmaf(a[i], b[j], acc[i][j]);
            }
            // store prefetched chunk into the other buffer
            if (kc < KDIM / BK - 1) {
                float* Bw = Bs + ((kc + 1) & 1) * (BK * SPAD);
                #pragma unroll
                for (int i = 0; i < 4; i++) {
                    int f = t + (i << 8);
                    int n = f >> 3, k = (f & 7) << 2;
                    Bw[(k + 0) * SPAD + n] = pre[i].x;
                    Bw[(k + 1) * SPAD + n] = pre[i].y;
                    Bw[(k + 2) * SPAD + n] = pre[i].z;
                    Bw[(k + 3) * SPAD + n] = pre[i].w;
                }
            }
            __syncthreads();
        }

        // ---- epilogue: score = x.v - 0.5||v||^2, running argmax ----
        #pragma unroll
        for (int j = 0; j < TN; j++) {
            int   vidx = n0 + ncol + j;
            float h    = g_hv2[vidx];
            #pragma unroll
            for (int i = 0; i < TM; i++) {
                float s = acc[i][j] - h;
                if (s > best[i]) { best[i] = s; bidx[i] = vidx; }
            }
        }
    }

    // ---- cross-thread reduction over the 16 column groups per row ----
    #pragma unroll
    for (int i = 0; i < TM; i++) {
        redS[(mrow + i) * 16 + tx] = best[i];
        redI[(mrow + i) * 16 + tx] = bidx[i];
    }
    __syncthreads();
    if (t < BM) {
        float bs = -3.4e38f;
        int   bi = 0x7FFFFFFF;
        #pragma unroll
        for (int j = 0; j < 16; j++) {
            float s  = redS[t * 16 + j];
            int   id = redI[t * 16 + j];
            if (s > bs || (s == bs && id < bi)) { bs = s; bi = id; }
        }
        int row = m0 + t;
        if (tok_f) tok_f[row] = (float)bi;
        if (tok_i) tok_i[row] = bi;
    }
}

// ---------------------------------------------------------------------------
extern "C" void kernel_launch(void* const* d_in, const int* in_sizes, int n_in,
                              void* d_out, int out_size) {
    const float* images = (const float*)d_in[0];   // [64,256,256] f32
    const float* vocab  = (const float*)d_in[1];   // [4096,256]  f32

    float* out       = (float*)d_out;
    float* patch_out = nullptr;
    float* tok_f     = nullptr;
    int*   tok_i     = nullptr;
    if (out_size >= N_PATCH_ELEMS + N_TOKENS) {
        patch_out = out;                 // patches, then tokens (as float)
        tok_f     = out + N_PATCH_ELEMS;
    } else if (out_size == N_PATCH_ELEMS) {
        patch_out = out;                 // patches only
    } else {
        tok_i = (int*)d_out;             // tokens only (int fallback)
    }

    cudaFuncSetAttribute(gemm_argmax_kernel,
                         cudaFuncAttributeMaxDynamicSharedMemorySize, SMEM_BYTES);

    // 1) patchify -> scratch (+ d_out patches region)
    {
        int nthr = N_PATCH_ELEMS / 4;
        patchify_kernel<<<(nthr + 255) / 256, 256>>>(images, patch_out);
    }
    // 2) 0.5*||v||^2
    {
        int nthr = VROWS * 32;
        vocab_norm_kernel<<<(nthr + 255) / 256, 256>>>(vocab);
    }
    // 3) fused GEMM + argmax -> tokens
    gemm_argmax_kernel<<<ROWS / BM, 256, SMEM_BYTES>>>(vocab, tok_f, tok_i);
}